// round 6
// baseline (speedup 1.0000x reference)
#include <cuda_runtime.h>
#include <cstdint>

#define B 4
#define L 2048
#define DIM 512
#define H 8
#define D 64
#define M_TOTAL (B * L)
#define SCALE 0.125f

// Scratch: __device__ globals (allocation-free rule). 4 x 16 MB.
__device__ float g_q[M_TOTAL * DIM];
__device__ float g_k[M_TOTAL * DIM];
__device__ float g_v[M_TOTAL * DIM];
__device__ float g_o[M_TOTAL * DIM];

__device__ __forceinline__ uint32_t f2tf(float x) {
    uint32_t r;
    asm("cvt.rna.tf32.f32 %0, %1;" : "=r"(r) : "f"(x));
    return r;
}

__device__ __forceinline__ void mma_tf32(float* d, const uint32_t* a,
                                         const uint32_t* b) {
    asm volatile(
        "mma.sync.aligned.m16n8k8.row.col.f32.tf32.tf32.f32 "
        "{%0,%1,%2,%3}, {%4,%5,%6,%7}, {%8,%9}, {%0,%1,%2,%3};"
        : "+f"(d[0]), "+f"(d[1]), "+f"(d[2]), "+f"(d[3])
        : "r"(a[0]), "r"(a[1]), "r"(a[2]), "r"(a[3]), "r"(b[0]), "r"(b[1]));
}

__device__ __forceinline__ uint32_t smem_u32(const void* p) {
    uint32_t a;
    asm("{ .reg .u64 t; cvta.to.shared.u64 t, %1; cvt.u32.u64 %0, t; }"
        : "=r"(a) : "l"(p));
    return a;
}

#define CP16(dst, src) \
    asm volatile("cp.async.cg.shared.global [%0], [%1], 16;" \
                 :: "r"(dst), "l"(src) : "memory")
#define CP_COMMIT() asm volatile("cp.async.commit_group;" ::: "memory")
#define CP_WAIT1() asm volatile("cp.async.wait_group 1;" ::: "memory")
#define CP_WAIT0() asm volatile("cp.async.wait_group 0;" ::: "memory")

// ---------------------------------------------------------------------------
// GEMM: Y[m][n] = sum_k X[m][k]*W[n][k] (x @ W.T), tf32 mma.sync,
// 2-stage cp.async pipeline. Block 128x128, 256 thr = 8 warps (4m x 2n).
// Stage buffers hold raw fp32; cvt to tf32 at fragment load.
// ---------------------------------------------------------------------------
#define PADG 36
#define GSTAGE (2 * 128 * PADG)              // As + Bs words per stage
#define GEMM_SMEM (2 * GSTAGE * 4)           // 73728 B

__device__ __forceinline__ void gemm_body(const float* __restrict__ X,
                                          const float* __restrict__ W,
                                          float* __restrict__ Y) {
    extern __shared__ uint32_t smg[];
    const int tid = threadIdx.x, lane = tid & 31, wid = tid >> 5;
    const int wm = wid & 3, wn = wid >> 2;
    const int mb = blockIdx.y * 128, nb = blockIdx.x * 128;
    const int lr = lane >> 2, lc = lane & 3;
    const uint32_t sb = smem_u32(smg);

    float acc[2][8][4];
#pragma unroll
    for (int i = 0; i < 2; i++)
#pragma unroll
        for (int j = 0; j < 8; j++)
#pragma unroll
            for (int c = 0; c < 4; c++) acc[i][j][c] = 0.0f;

    // cp.async one 128x32 chunk pair (A and B) into stage s.
    // 128 rows x 8 float4 cols per matrix = 1024 float4; x2 matrices = 2048;
    // 256 threads -> 8 CP16 each. t&1 selects A/B, t>>1 selects row quarter.
    const int cr = tid >> 3, cc4 = tid & 7;  // rows 0..31, col4 0..7
    auto issue = [&](int kt, int s) {
        const int k0 = kt * 32;
        uint32_t base = sb + (uint32_t)s * GSTAGE * 4;
#pragma unroll
        for (int t = 0; t < 8; t++) {
            int r = cr + (t >> 1) * 32;      // 0..127
            const float* src = (t & 1) ? W + (size_t)(nb + r) * DIM + k0 + cc4 * 4
                                       : X + (size_t)(mb + r) * DIM + k0 + cc4 * 4;
            uint32_t dst = base + ((t & 1) ? 128 * PADG * 4u : 0u) +
                           (uint32_t)(r * PADG + cc4 * 4) * 4;
            CP16(dst, src);
        }
        CP_COMMIT();
    };

    issue(0, 0);
    for (int kt = 0; kt < 16; kt++) {
        if (kt < 15) { issue(kt + 1, (kt + 1) & 1); CP_WAIT1(); }
        else CP_WAIT0();
        __syncthreads();

        const float* As = (const float*)(smg + ((kt & 1) ? GSTAGE : 0));
        const float* Bs = As + 128 * PADG;
#pragma unroll
        for (int ks = 0; ks < 4; ks++) {
            const int kk = ks * 8;
            uint32_t a[2][4], b[8][2];
#pragma unroll
            for (int mt = 0; mt < 2; mt++) {
                int r0 = wm * 32 + mt * 16 + lr;
                a[mt][0] = f2tf(As[r0 * PADG + kk + lc]);
                a[mt][1] = f2tf(As[(r0 + 8) * PADG + kk + lc]);
                a[mt][2] = f2tf(As[r0 * PADG + kk + lc + 4]);
                a[mt][3] = f2tf(As[(r0 + 8) * PADG + kk + lc + 4]);
            }
#pragma unroll
            for (int nt = 0; nt < 8; nt++) {
                int n0 = wn * 64 + nt * 8 + lr;
                b[nt][0] = f2tf(Bs[n0 * PADG + kk + lc]);
                b[nt][1] = f2tf(Bs[n0 * PADG + kk + lc + 4]);
            }
#pragma unroll
            for (int mt = 0; mt < 2; mt++)
#pragma unroll
                for (int nt = 0; nt < 8; nt++)
                    mma_tf32(acc[mt][nt], a[mt], b[nt]);
        }
        __syncthreads();
    }

#pragma unroll
    for (int mt = 0; mt < 2; mt++) {
        int r0 = mb + wm * 32 + mt * 16 + lr;
#pragma unroll
        for (int nt = 0; nt < 8; nt++) {
            int c0 = nb + wn * 64 + nt * 8 + 2 * lc;
            *(float2*)(Y + (size_t)r0 * DIM + c0) =
                make_float2(acc[mt][nt][0], acc[mt][nt][1]);
            *(float2*)(Y + (size_t)(r0 + 8) * DIM + c0) =
                make_float2(acc[mt][nt][2], acc[mt][nt][3]);
        }
    }
}

__global__ __launch_bounds__(256, 2) void qkv_gemm(const float* __restrict__ x,
                                                   const float* __restrict__ wq,
                                                   const float* __restrict__ wk,
                                                   const float* __restrict__ wv) {
    const float* W = (blockIdx.z == 0) ? wq : (blockIdx.z == 1) ? wk : wv;
    float* Y = (blockIdx.z == 0) ? g_q : (blockIdx.z == 1) ? g_k : g_v;
    gemm_body(x, W, Y);
}

__global__ __launch_bounds__(256, 2) void out_gemm(const float* __restrict__ wo,
                                                   float* __restrict__ out) {
    gemm_body(g_o, wo, out);
}

// ---------------------------------------------------------------------------
// Flash attention, tf32 mma.sync, single-pass softmax, P in registers,
// key-split warp pairs, 2-stage cp.async K/V pipeline.
// 512 threads = 16 warps: wq=wid>>1 owns q rows [wq*16,+16); wk=wid&1 owns
// keys [wk*32,+32) per 64-key tile. Stage = Ks[64][68] + Vs[64][72] raw fp32.
// Q staged (tf32) in stage1 while tile0 prefetches into stage0.
// ---------------------------------------------------------------------------
#define PADQ 68
#define PADV 72
#define KS_W (64 * PADQ)                     // 4352 words
#define VS_W (64 * PADV)                     // 4608 words
#define ASTAGE (KS_W + VS_W)                 // 8960 words per stage
#define ATTN_SMEM (2 * ASTAGE * 4)           // 71680 B

__global__ __launch_bounds__(512, 1) void attn_tc() {
    extern __shared__ uint32_t sm[];
    const int tid = threadIdx.x, lane = tid & 31, wid = tid >> 5;
    const int lr = lane >> 2, lc = lane & 3;
    const int wq_ = wid >> 1, wk_ = wid & 1;
    const int bh = blockIdx.y, b_ = bh >> 3, h_ = bh & 7;
    const int q0 = blockIdx.x * 128;
    const uint32_t sb = smem_u32(sm);

    const float* Qg = g_q + (size_t)b_ * L * DIM + h_ * 64;
    const float* Kg = g_k + (size_t)b_ * L * DIM + h_ * 64;
    const float* Vg = g_v + (size_t)b_ * L * DIM + h_ * 64;

    // cp.async one K/V tile (64x64 fp32 each) into stage s.
    // 64 rows x 16 float4 per matrix = 1024; x2 = 2048; 512 thr -> 4 each.
    const int tr = tid >> 4, tc4 = tid & 15; // rows 0..31, col4 0..15
    auto issue = [&](int t, int s) {
        const int k0g = t * 64;
        uint32_t base = sb + (uint32_t)s * ASTAGE * 4;
#pragma unroll
        for (int u = 0; u < 4; u++) {
            int r = tr + (u >> 1) * 32;      // 0..63
            const float* src = (u & 1) ? Vg + (size_t)(k0g + r) * DIM + tc4 * 4
                                       : Kg + (size_t)(k0g + r) * DIM + tc4 * 4;
            uint32_t dst = base + ((u & 1) ? (uint32_t)(r * PADV + tc4 * 4) + KS_W
                                           : (uint32_t)(r * PADQ + tc4 * 4)) * 4;
            CP16(dst, src);
        }
        CP_COMMIT();
    };

    issue(0, 0);                             // tile0 -> stage0 (overlaps Q work)

    // Stage Q (tf32) into stage1 region, then extract fragments.
    uint32_t* Qs = sm + ASTAGE;              // 128 x 68 = 8704 <= 8960 words
#pragma unroll
    for (int t = 0; t < 4; t++) {
        int idx = tid + t * 512;
        int r = idx >> 4, c4 = idx & 15;
        float4 x = *(const float4*)(Qg + (size_t)(q0 + r) * DIM + c4 * 4);
        *(uint4*)(Qs + r * PADQ + c4 * 4) =
            make_uint4(f2tf(x.x), f2tf(x.y), f2tf(x.z), f2tf(x.w));
    }
    __syncthreads();
    uint32_t aq[8][4];
    {
        int r0 = wq_ * 16 + lr;
#pragma unroll
        for (int ks = 0; ks < 8; ks++) {
            int kk = ks * 8;
            aq[ks][0] = Qs[r0 * PADQ + kk + lc];
            aq[ks][1] = Qs[(r0 + 8) * PADQ + kk + lc];
            aq[ks][2] = Qs[r0 * PADQ + kk + lc + 4];
            aq[ks][3] = Qs[(r0 + 8) * PADQ + kk + lc + 4];
        }
    }
    __syncthreads();                         // stage1 free for tile1

    float o[8][4];
#pragma unroll
    for (int nt = 0; nt < 8; nt++)
#pragma unroll
        for (int c = 0; c < 4; c++) o[nt][c] = 0.0f;
    float l0 = 0.0f, l1 = 0.0f;

    const int row0 = q0 + wq_ * 16 + lr;
    const int row1 = row0 + 8;
    const int src1 = (lane & 28) | (lc >> 1);
    const int src2 = src1 + 2;
    const bool oddc = (lc & 1);

    for (int t = 0; t < 32; t++) {
        if (t < 31) { issue(t + 1, (t + 1) & 1); CP_WAIT1(); }
        else CP_WAIT0();
        __syncthreads();

        const float* Ks = (const float*)(sm + ((t & 1) ? ASTAGE : 0));
        const float* Vs = Ks + KS_W;
        const int k0g = t * 64;

        // S = Q @ K^T : 16 q x 32 keys per warp.
        float s[4][4];
#pragma unroll
        for (int nt = 0; nt < 4; nt++)
#pragma unroll
            for (int c = 0; c < 4; c++) s[nt][c] = 0.0f;
#pragma unroll
        for (int ks = 0; ks < 8; ks++) {
            const int kk = ks * 8;
            uint32_t bkf[4][2];
#pragma unroll
            for (int nt = 0; nt < 4; nt++) {
                int key = wk_ * 32 + nt * 8 + lr;
                bkf[nt][0] = f2tf(Ks[key * PADQ + kk + lc]);
                bkf[nt][1] = f2tf(Ks[key * PADQ + kk + lc + 4]);
            }
#pragma unroll
            for (int nt = 0; nt < 4; nt++) mma_tf32(s[nt], aq[ks], bkf[nt]);
        }

        // p = exp(s*SCALE); diagonal -> 0; accumulate row sums.
#pragma unroll
        for (int nt = 0; nt < 4; nt++) {
            int key = k0g + wk_ * 32 + nt * 8 + 2 * lc;
            float p0 = __expf(s[nt][0] * SCALE);
            float p1 = __expf(s[nt][1] * SCALE);
            float p2 = __expf(s[nt][2] * SCALE);
            float p3 = __expf(s[nt][3] * SCALE);
            if (key == row0) p0 = 0.0f;
            if (key + 1 == row0) p1 = 0.0f;
            if (key == row1) p2 = 0.0f;
            if (key + 1 == row1) p3 = 0.0f;
            l0 += p0 + p1;
            l1 += p2 + p3;
            s[nt][0] = p0; s[nt][1] = p1; s[nt][2] = p2; s[nt][3] = p3;
        }

        // O += P @ V, P fragments via warp shuffles.
#pragma unroll
        for (int ksl = 0; ksl < 4; ksl++) {
            float e0 = __shfl_sync(0xffffffffu, s[ksl][0], src1);
            float e1 = __shfl_sync(0xffffffffu, s[ksl][1], src1);
            float e2 = __shfl_sync(0xffffffffu, s[ksl][2], src1);
            float e3 = __shfl_sync(0xffffffffu, s[ksl][3], src1);
            float f0 = __shfl_sync(0xffffffffu, s[ksl][0], src2);
            float f1 = __shfl_sync(0xffffffffu, s[ksl][1], src2);
            float f2 = __shfl_sync(0xffffffffu, s[ksl][2], src2);
            float f3 = __shfl_sync(0xffffffffu, s[ksl][3], src2);
            uint32_t ap[4];
            ap[0] = f2tf(oddc ? e1 : e0);
            ap[1] = f2tf(oddc ? e3 : e2);
            ap[2] = f2tf(oddc ? f1 : f0);
            ap[3] = f2tf(oddc ? f3 : f2);

            const int kk = wk_ * 32 + ksl * 8;
            uint32_t bv[8][2];
#pragma unroll
            for (int nt = 0; nt < 8; nt++) {
                int d0 = nt * 8 + lr;
                bv[nt][0] = f2tf(Vs[(kk + lc) * PADV + d0]);
                bv[nt][1] = f2tf(Vs[(kk + lc + 4) * PADV + d0]);
            }
#pragma unroll
            for (int nt = 0; nt < 8; nt++) mma_tf32(o[nt], ap, bv[nt]);
        }
        __syncthreads();                     // free stage (t&1) for tile t+2
    }

    // Merge key-half pairs via smem (stage0 region reused; last tile = stage1).
    float* OS = (float*)sm;                  // [8][32][32] = 32 KB
    float* LS = (float*)(sm + 8 * 32 * 32);  // [8][32][2]
    if (wk_ == 1) {
        float* dst = OS + ((size_t)wq_ * 32 + lane) * 32;
#pragma unroll
        for (int nt = 0; nt < 8; nt++)
#pragma unroll
            for (int c = 0; c < 4; c++) dst[nt * 4 + c] = o[nt][c];
        LS[(wq_ * 32 + lane) * 2 + 0] = l0;
        LS[(wq_ * 32 + lane) * 2 + 1] = l1;
    }
    __syncthreads();
    if (wk_ == 0) {
        const float* srcp = OS + ((size_t)wq_ * 32 + lane) * 32;
#pragma unroll
        for (int nt = 0; nt < 8; nt++)
#pragma unroll
            for (int c = 0; c < 4; c++) o[nt][c] += srcp[nt * 4 + c];
        l0 += LS[(wq_ * 32 + lane) * 2 + 0];
        l1 += LS[(wq_ * 32 + lane) * 2 + 1];
#pragma unroll
        for (int off = 1; off <= 2; off <<= 1) {
            l0 += __shfl_xor_sync(0xffffffffu, l0, off);
            l1 += __shfl_xor_sync(0xffffffffu, l1, off);
        }
        const float inv0 = 1.0f / l0, inv1 = 1.0f / l1;
        float* Og = g_o + ((size_t)b_ * L) * DIM + h_ * 64;
#pragma unroll
        for (int nt = 0; nt < 8; nt++) {
            int c0 = nt * 8 + 2 * lc;
            *(float2*)(Og + (size_t)row0 * DIM + c0) =
                make_float2(o[nt][0] * inv0, o[nt][1] * inv0);
            *(float2*)(Og + (size_t)row1 * DIM + c0) =
                make_float2(o[nt][2] * inv1, o[nt][3] * inv1);
        }
    }
}

// ---------------------------------------------------------------------------
extern "C" void kernel_launch(void* const* d_in, const int* in_sizes, int n_in,
                              void* d_out, int out_size) {
    const float* x  = (const float*)d_in[0];
    const float* wq = (const float*)d_in[1];
    const float* wk = (const float*)d_in[2];
    const float* wv = (const float*)d_in[3];
    const float* wo = (const float*)d_in[4];
    float* out = (float*)d_out;

    cudaFuncSetAttribute(qkv_gemm, cudaFuncAttributeMaxDynamicSharedMemorySize,
                         GEMM_SMEM);
    cudaFuncSetAttribute(out_gemm, cudaFuncAttributeMaxDynamicSharedMemorySize,
                         GEMM_SMEM);
    cudaFuncSetAttribute(attn_tc, cudaFuncAttributeMaxDynamicSharedMemorySize,
                         ATTN_SMEM);

    qkv_gemm<<<dim3(4, 64, 3), 256, GEMM_SMEM>>>(x, wq, wk, wv);
    attn_tc<<<dim3(L / 128, B * H), 512, ATTN_SMEM>>>();
    out_gemm<<<dim3(4, 64), 256, GEMM_SMEM>>>(wo, out);
}

// round 7
// speedup vs baseline: 1.7180x; 1.7180x over previous
#include <cuda_runtime.h>
#include <cuda_fp16.h>
#include <cstdint>

#define B 4
#define L 2048
#define DIM 512
#define H 8
#define D 64
#define M_TOTAL (B * L)
#define SCALE 0.125f

// fp16 scratch (allocation-free rule: __device__ globals).
__device__ __half hx[M_TOTAL * DIM];
__device__ __half hw[4 * DIM * DIM];         // wq, wk, wv, wo
__device__ __half g_q[M_TOTAL * DIM];
__device__ __half g_k[M_TOTAL * DIM];
__device__ __half g_v[M_TOTAL * DIM];
__device__ __half g_o[M_TOTAL * DIM];

__device__ __forceinline__ uint32_t pack2(float a, float b) {
    __half2 h = __floats2half2_rn(a, b);
    return *(uint32_t*)&h;
}

__device__ __forceinline__ void mma_f16(float* d, const uint32_t* a,
                                        const uint32_t* b) {
    asm volatile(
        "mma.sync.aligned.m16n8k16.row.col.f32.f16.f16.f32 "
        "{%0,%1,%2,%3}, {%4,%5,%6,%7}, {%8,%9}, {%0,%1,%2,%3};"
        : "+f"(d[0]), "+f"(d[1]), "+f"(d[2]), "+f"(d[3])
        : "r"(a[0]), "r"(a[1]), "r"(a[2]), "r"(a[3]), "r"(b[0]), "r"(b[1]));
}

__device__ __forceinline__ uint32_t smem_u32(const void* p) {
    uint32_t a;
    asm("{ .reg .u64 t; cvta.to.shared.u64 t, %1; cvt.u32.u64 %0, t; }"
        : "=r"(a) : "l"(p));
    return a;
}

#define CP16(dst, src) \
    asm volatile("cp.async.cg.shared.global [%0], [%1], 16;" \
                 :: "r"(dst), "l"(src) : "memory")
#define CP_COMMIT() asm volatile("cp.async.commit_group;" ::: "memory")
#define CP_WAIT1() asm volatile("cp.async.wait_group 1;" ::: "memory")
#define CP_WAIT0() asm volatile("cp.async.wait_group 0;" ::: "memory")

// ---------------------------------------------------------------------------
// fp32 -> fp16 conversion (x and the four weight matrices).
// ---------------------------------------------------------------------------
__global__ void cvt_kernel(const float* __restrict__ src,
                           __half* __restrict__ dst, int n4) {
    int i = blockIdx.x * blockDim.x + threadIdx.x;
    int stride = gridDim.x * blockDim.x;
    for (; i < n4; i += stride) {
        float4 v = ((const float4*)src)[i];
        ((__half2*)dst)[2 * i] = __floats2half2_rn(v.x, v.y);
        ((__half2*)dst)[2 * i + 1] = __floats2half2_rn(v.z, v.w);
    }
}

// ---------------------------------------------------------------------------
// GEMM: Y[m][n] = sum_k X[m][k]*W[n][k] (x @ W.T), fp16 m16n8k16, f32 accum.
// Block 128x128, 256 thr = 8 warps (4m x 2n), warp tile 32x64, K-chunk 64,
// 2-stage cp.async pipeline. vmode 0/1/2 -> g_q/k/v (fp16); 3 -> out (fp32).
// ---------------------------------------------------------------------------
#define PADH 72                               // halves per row (144 B)
#define GST_H (2 * 128 * PADH)                // A+B halves per stage
#define GEMM_SMEM (2 * GST_H * 2)             // 73728 B

__global__ __launch_bounds__(256, 2) void gemm_f16(float* __restrict__ outp,
                                                   int vmode) {
    extern __shared__ __half smg[];
    const int tid = threadIdx.x, lane = tid & 31, wid = tid >> 5;
    const int wm = wid & 3, wn = wid >> 2;
    const int mb = blockIdx.y * 128, nb = blockIdx.x * 128;
    const int lr = lane >> 2, lc = lane & 3;
    const uint32_t sb = smem_u32(smg);

    const __half* X = (vmode == 3) ? g_o : hx;
    const __half* W = hw + (size_t)vmode * DIM * DIM;
    __half* Yh = (vmode == 0) ? g_q : (vmode == 1) ? g_k : g_v;

    float acc[2][8][4];
#pragma unroll
    for (int i = 0; i < 2; i++)
#pragma unroll
        for (int j = 0; j < 8; j++)
#pragma unroll
            for (int c = 0; c < 4; c++) acc[i][j][c] = 0.0f;

    // cp.async one 128x64-half chunk pair into stage s. 8 CP16 per thread.
    const int cr = tid >> 3, cc = tid & 7;    // rows 0..31, 16B-chunks 0..7
    auto issue = [&](int kt, int s) {
        const int k0 = kt * 64;
        uint32_t base = sb + (uint32_t)s * GST_H * 2;
#pragma unroll
        for (int t = 0; t < 8; t++) {
            int r = cr + (t >> 1) * 32;       // 0..127
            const __half* src = (t & 1) ? W + (size_t)(nb + r) * DIM + k0 + cc * 8
                                        : X + (size_t)(mb + r) * DIM + k0 + cc * 8;
            uint32_t dst = base + ((t & 1) ? (uint32_t)(128 * PADH * 2) : 0u) +
                           (uint32_t)(r * PADH + cc * 8) * 2;
            CP16(dst, src);
        }
        CP_COMMIT();
    };

    issue(0, 0);
    for (int kt = 0; kt < 8; kt++) {
        if (kt < 7) { issue(kt + 1, (kt + 1) & 1); CP_WAIT1(); }
        else CP_WAIT0();
        __syncthreads();

        const __half* As = smg + ((kt & 1) ? GST_H : 0);
        const __half* Bs = As + 128 * PADH;
#pragma unroll
        for (int ks = 0; ks < 4; ks++) {
            const int kk = ks * 16;
            uint32_t a[2][4], b[8][2];
#pragma unroll
            for (int mt = 0; mt < 2; mt++) {
                int r0 = wm * 32 + mt * 16 + lr;
                a[mt][0] = *(const uint32_t*)&As[r0 * PADH + kk + 2 * lc];
                a[mt][1] = *(const uint32_t*)&As[(r0 + 8) * PADH + kk + 2 * lc];
                a[mt][2] = *(const uint32_t*)&As[r0 * PADH + kk + 2 * lc + 8];
                a[mt][3] = *(const uint32_t*)&As[(r0 + 8) * PADH + kk + 2 * lc + 8];
            }
#pragma unroll
            for (int nt = 0; nt < 8; nt++) {
                int n0 = wn * 64 + nt * 8 + lr;
                b[nt][0] = *(const uint32_t*)&Bs[n0 * PADH + kk + 2 * lc];
                b[nt][1] = *(const uint32_t*)&Bs[n0 * PADH + kk + 2 * lc + 8];
            }
#pragma unroll
            for (int mt = 0; mt < 2; mt++)
#pragma unroll
                for (int nt = 0; nt < 8; nt++)
                    mma_f16(acc[mt][nt], a[mt], b[nt]);
        }
        __syncthreads();
    }

#pragma unroll
    for (int mt = 0; mt < 2; mt++) {
        int r0 = mb + wm * 32 + mt * 16 + lr;
#pragma unroll
        for (int nt = 0; nt < 8; nt++) {
            int c0 = nb + wn * 64 + nt * 8 + 2 * lc;
            if (vmode == 3) {
                *(float2*)(outp + (size_t)r0 * DIM + c0) =
                    make_float2(acc[mt][nt][0], acc[mt][nt][1]);
                *(float2*)(outp + (size_t)(r0 + 8) * DIM + c0) =
                    make_float2(acc[mt][nt][2], acc[mt][nt][3]);
            } else {
                *(uint32_t*)(Yh + (size_t)r0 * DIM + c0) =
                    pack2(acc[mt][nt][0], acc[mt][nt][1]);
                *(uint32_t*)(Yh + (size_t)(r0 + 8) * DIM + c0) =
                    pack2(acc[mt][nt][2], acc[mt][nt][3]);
            }
        }
    }
}

// ---------------------------------------------------------------------------
// Flash attention, fp16 m16n8k16, f32 accum, single-pass softmax, P packed
// directly into A fragments (fp16 C layout == A layout), key-split warp pairs,
// 2-stage cp.async K/V pipeline.
// 512 thr = 16 warps: wq=wid>>1 owns q rows [wq*16,+16); wk=wid&1 owns keys
// [wk*32,+32) of each 64-key tile.
// ---------------------------------------------------------------------------
#define PADA 72
#define KS_H (64 * PADA)                      // 4608 halves
#define ASTAGE_H (2 * KS_H)                   // K + V per stage, 9216 halves
#define ATTN_SMEM (2 * ASTAGE_H * 2)          // 36864 B

__global__ __launch_bounds__(512, 1) void attn_f16() {
    extern __shared__ __half smh[];
    const int tid = threadIdx.x, lane = tid & 31, wid = tid >> 5;
    const int lr = lane >> 2, lc = lane & 3;
    const int wq_ = wid >> 1, wk_ = wid & 1;
    const int bh = blockIdx.y, b_ = bh >> 3, h_ = bh & 7;
    const int q0 = blockIdx.x * 128;
    const uint32_t sb = smem_u32(smh);

    const __half* Qg = g_q + (size_t)b_ * L * DIM + h_ * 64;
    const __half* Kg = g_k + (size_t)b_ * L * DIM + h_ * 64;
    const __half* Vg = g_v + (size_t)b_ * L * DIM + h_ * 64;

    // cp.async one K/V tile (64x64 halves each): 2 CP16 per thread.
    const int ar = tid >> 3, ac = tid & 7;
    auto issue = [&](int t, int s) {
        const int k0g = t * 64;
        uint32_t base = sb + (uint32_t)s * ASTAGE_H * 2;
        CP16(base + (uint32_t)(ar * PADA + ac * 8) * 2,
             Kg + (size_t)(k0g + ar) * DIM + ac * 8);
        CP16(base + (uint32_t)(KS_H + ar * PADA + ac * 8) * 2,
             Vg + (size_t)(k0g + ar) * DIM + ac * 8);
        CP_COMMIT();
    };

    issue(0, 0);                              // tile0 -> stage0

    // Stage Q [128][64] halves into stage1, extract A fragments.
    __half* Qs = smh + ASTAGE_H;
#pragma unroll
    for (int t = 0; t < 2; t++) {
        int idx = tid + t * 512;              // 0..1023
        int r = idx >> 3, c = idx & 7;
        *(uint4*)&Qs[r * PADA + c * 8] =
            *(const uint4*)(Qg + (size_t)(q0 + r) * DIM + c * 8);
    }
    __syncthreads();
    uint32_t aq[4][4];
    {
        int r0 = wq_ * 16 + lr;
#pragma unroll
        for (int ks = 0; ks < 4; ks++) {
            int kk = ks * 16;
            aq[ks][0] = *(const uint32_t*)&Qs[r0 * PADA + kk + 2 * lc];
            aq[ks][1] = *(const uint32_t*)&Qs[(r0 + 8) * PADA + kk + 2 * lc];
            aq[ks][2] = *(const uint32_t*)&Qs[r0 * PADA + kk + 2 * lc + 8];
            aq[ks][3] = *(const uint32_t*)&Qs[(r0 + 8) * PADA + kk + 2 * lc + 8];
        }
    }
    __syncthreads();                          // stage1 free for tile1

    float o[8][4];
#pragma unroll
    for (int nt = 0; nt < 8; nt++)
#pragma unroll
        for (int c = 0; c < 4; c++) o[nt][c] = 0.0f;
    float l0 = 0.0f, l1 = 0.0f;

    const int row0 = q0 + wq_ * 16 + lr;
    const int row1 = row0 + 8;

    for (int t = 0; t < 32; t++) {
        if (t < 31) { issue(t + 1, (t + 1) & 1); CP_WAIT1(); }
        else CP_WAIT0();
        __syncthreads();

        const __half* Ks = smh + ((t & 1) ? ASTAGE_H : 0);
        const __half* Vs = Ks + KS_H;
        const int k0g = t * 64;

        // S = Q @ K^T : 16 q x 32 keys per warp (4 n-tiles).
        float s[4][4];
#pragma unroll
        for (int nt = 0; nt < 4; nt++)
#pragma unroll
            for (int c = 0; c < 4; c++) s[nt][c] = 0.0f;
#pragma unroll
        for (int ks = 0; ks < 4; ks++) {
            const int kk = ks * 16;
            uint32_t bk[4][2];
#pragma unroll
            for (int nt = 0; nt < 4; nt++) {
                int key = wk_ * 32 + nt * 8 + lr;
                bk[nt][0] = *(const uint32_t*)&Ks[key * PADA + kk + 2 * lc];
                bk[nt][1] = *(const uint32_t*)&Ks[key * PADA + kk + 2 * lc + 8];
            }
#pragma unroll
            for (int nt = 0; nt < 4; nt++) mma_f16(s[nt], aq[ks], bk[nt]);
        }

        // p = exp(s*SCALE); diagonal -> 0; row sums.
#pragma unroll
        for (int nt = 0; nt < 4; nt++) {
            int key = k0g + wk_ * 32 + nt * 8 + 2 * lc;
            float p0 = __expf(s[nt][0] * SCALE);
            float p1 = __expf(s[nt][1] * SCALE);
            float p2 = __expf(s[nt][2] * SCALE);
            float p3 = __expf(s[nt][3] * SCALE);
            if (key == row0) p0 = 0.0f;
            if (key + 1 == row0) p1 = 0.0f;
            if (key == row1) p2 = 0.0f;
            if (key + 1 == row1) p3 = 0.0f;
            l0 += p0 + p1;
            l1 += p2 + p3;
            s[nt][0] = p0; s[nt][1] = p1; s[nt][2] = p2; s[nt][3] = p3;
        }

        // O += P @ V.  fp16 C layout == A layout: pack s directly into A regs.
#pragma unroll
        for (int ksl = 0; ksl < 2; ksl++) {
            uint32_t ap[4];
            ap[0] = pack2(s[2 * ksl][0], s[2 * ksl][1]);
            ap[1] = pack2(s[2 * ksl][2], s[2 * ksl][3]);
            ap[2] = pack2(s[2 * ksl + 1][0], s[2 * ksl + 1][1]);
            ap[3] = pack2(s[2 * ksl + 1][2], s[2 * ksl + 1][3]);

            const int kkv = wk_ * 32 + ksl * 16;
            uint32_t bv[8][2];
#pragma unroll
            for (int nt = 0; nt < 8; nt++) {
                int d0 = nt * 8 + lr;
                __half v00 = Vs[(kkv + 2 * lc) * PADA + d0];
                __half v01 = Vs[(kkv + 2 * lc + 1) * PADA + d0];
                __half v10 = Vs[(kkv + 2 * lc + 8) * PADA + d0];
                __half v11 = Vs[(kkv + 2 * lc + 9) * PADA + d0];
                __half2 h0 = __halves2half2(v00, v01);
                __half2 h1 = __halves2half2(v10, v11);
                bv[nt][0] = *(uint32_t*)&h0;
                bv[nt][1] = *(uint32_t*)&h1;
            }
#pragma unroll
            for (int nt = 0; nt < 8; nt++) mma_f16(o[nt], ap, bv[nt]);
        }
        __syncthreads();                      // free stage (t&1)
    }

    // Merge key-half pairs via smem (stage0 region reused).
    float* OS = (float*)smh;                  // [8][32][32] = 32 KB
    float* LS = (float*)smh + 8 * 32 * 32;    // [8][32][2]
    if (wk_ == 1) {
        float* dst = OS + ((size_t)wq_ * 32 + lane) * 32;
#pragma unroll
        for (int nt = 0; nt < 8; nt++)
#pragma unroll
            for (int c = 0; c < 4; c++) dst[nt * 4 + c] = o[nt][c];
        LS[(wq_ * 32 + lane) * 2 + 0] = l0;
        LS[(wq_ * 32 + lane) * 2 + 1] = l1;
    }
    __syncthreads();
    if (wk_ == 0) {
        const float* srcp = OS + ((size_t)wq_ * 32 + lane) * 32;
#pragma unroll
        for (int nt = 0; nt < 8; nt++)
#pragma unroll
            for (int c = 0; c < 4; c++) o[nt][c] += srcp[nt * 4 + c];
        l0 += LS[(wq_ * 32 + lane) * 2 + 0];
        l1 += LS[(wq_ * 32 + lane) * 2 + 1];
#pragma unroll
        for (int off = 1; off <= 2; off <<= 1) {
            l0 += __shfl_xor_sync(0xffffffffu, l0, off);
            l1 += __shfl_xor_sync(0xffffffffu, l1, off);
        }
        const float inv0 = 1.0f / l0, inv1 = 1.0f / l1;
        __half* Og = g_o + ((size_t)b_ * L) * DIM + h_ * 64;
#pragma unroll
        for (int nt = 0; nt < 8; nt++) {
            int c0 = nt * 8 + 2 * lc;
            *(uint32_t*)(Og + (size_t)row0 * DIM + c0) =
                pack2(o[nt][0] * inv0, o[nt][1] * inv0);
            *(uint32_t*)(Og + (size_t)row1 * DIM + c0) =
                pack2(o[nt][2] * inv1, o[nt][3] * inv1);
        }
    }
}

// ---------------------------------------------------------------------------
extern "C" void kernel_launch(void* const* d_in, const int* in_sizes, int n_in,
                              void* d_out, int out_size) {
    const float* x  = (const float*)d_in[0];
    const float* wq = (const float*)d_in[1];
    const float* wk = (const float*)d_in[2];
    const float* wv = (const float*)d_in[3];
    const float* wo = (const float*)d_in[4];
    float* out = (float*)d_out;

    cudaFuncSetAttribute(gemm_f16, cudaFuncAttributeMaxDynamicSharedMemorySize,
                         GEMM_SMEM);
    cudaFuncSetAttribute(attn_f16, cudaFuncAttributeMaxDynamicSharedMemorySize,
                         ATTN_SMEM);

    __half* d_hx; cudaGetSymbolAddress((void**)&d_hx, hx);
    __half* d_hw; cudaGetSymbolAddress((void**)&d_hw, hw);

    cvt_kernel<<<256, 256>>>(x, d_hx, M_TOTAL * DIM / 4);
    cvt_kernel<<<64, 256>>>(wq, d_hw + 0 * DIM * DIM, DIM * DIM / 4);
    cvt_kernel<<<64, 256>>>(wk, d_hw + 1 * DIM * DIM, DIM * DIM / 4);
    cvt_kernel<<<64, 256>>>(wv, d_hw + 2 * DIM * DIM, DIM * DIM / 4);
    cvt_kernel<<<64, 256>>>(wo, d_hw + 3 * DIM * DIM, DIM * DIM / 4);

    dim3 gg(DIM / 128, M_TOTAL / 128);        // 4 x 64
    gemm_f16<<<dim3(4, 64, 1), 256, GEMM_SMEM>>>(nullptr, 0);
    gemm_f16<<<dim3(4, 64, 1), 256, GEMM_SMEM>>>(nullptr, 1);
    gemm_f16<<<dim3(4, 64, 1), 256, GEMM_SMEM>>>(nullptr, 2);
    attn_f16<<<dim3(L / 128, B * H), 512, ATTN_SMEM>>>();
    gemm_f16<<<gg, 256, GEMM_SMEM>>>(out, 3);
}

// round 8
// speedup vs baseline: 2.1845x; 1.2715x over previous
#include <cuda_runtime.h>
#include <cuda_fp16.h>
#include <cstdint>

#define B 4
#define L 2048
#define DIM 512
#define H 8
#define D 64
#define M_TOTAL (B * L)
#define SCALE 0.125f

// fp16 scratch (allocation-free rule: __device__ globals).
__device__ __half hx[M_TOTAL * DIM];
__device__ __half hw[4 * DIM * DIM];         // wq, wk, wv, wo
__device__ __half g_q[M_TOTAL * DIM];
__device__ __half g_k[M_TOTAL * DIM];
__device__ __half g_v[M_TOTAL * DIM];
__device__ __half g_o[M_TOTAL * DIM];

__device__ __forceinline__ uint32_t pack2(float a, float b) {
    __half2 h = __floats2half2_rn(a, b);
    return *(uint32_t*)&h;
}

__device__ __forceinline__ void mma_f16(float* d, const uint32_t* a,
                                        const uint32_t* b) {
    asm volatile(
        "mma.sync.aligned.m16n8k16.row.col.f32.f16.f16.f32 "
        "{%0,%1,%2,%3}, {%4,%5,%6,%7}, {%8,%9}, {%0,%1,%2,%3};"
        : "+f"(d[0]), "+f"(d[1]), "+f"(d[2]), "+f"(d[3])
        : "r"(a[0]), "r"(a[1]), "r"(a[2]), "r"(a[3]), "r"(b[0]), "r"(b[1]));
}

__device__ __forceinline__ uint32_t smem_u32(const void* p) {
    uint32_t a;
    asm("{ .reg .u64 t; cvta.to.shared.u64 t, %1; cvt.u32.u64 %0, t; }"
        : "=r"(a) : "l"(p));
    return a;
}

#define LDSM4(d0, d1, d2, d3, a) \
    asm volatile("ldmatrix.sync.aligned.m8n8.x4.shared.b16 {%0,%1,%2,%3}, [%4];" \
                 : "=r"(d0), "=r"(d1), "=r"(d2), "=r"(d3) : "r"(a))
#define LDSM4T(d0, d1, d2, d3, a) \
    asm volatile("ldmatrix.sync.aligned.m8n8.x4.trans.shared.b16 {%0,%1,%2,%3}, [%4];" \
                 : "=r"(d0), "=r"(d1), "=r"(d2), "=r"(d3) : "r"(a))

#define CP16(dst, src) \
    asm volatile("cp.async.cg.shared.global [%0], [%1], 16;" \
                 :: "r"(dst), "l"(src) : "memory")
#define CP_COMMIT() asm volatile("cp.async.commit_group;" ::: "memory")
#define CP_WAIT1() asm volatile("cp.async.wait_group 1;" ::: "memory")
#define CP_WAIT0() asm volatile("cp.async.wait_group 0;" ::: "memory")

// ---------------------------------------------------------------------------
// fp32 -> fp16 conversion, one launch (blockIdx.y selects tensor).
// ---------------------------------------------------------------------------
__global__ void cvt_all(const float* __restrict__ x,  const float* __restrict__ wq,
                        const float* __restrict__ wk, const float* __restrict__ wv,
                        const float* __restrict__ wo) {
    const int sel = blockIdx.y;
    const float* src;
    __half* dst;
    int n4;
    if (sel == 0) { src = x;  dst = hx;                 n4 = M_TOTAL * DIM / 4; }
    else if (sel == 1) { src = wq; dst = hw;                n4 = DIM * DIM / 4; }
    else if (sel == 2) { src = wk; dst = hw + DIM * DIM;    n4 = DIM * DIM / 4; }
    else if (sel == 3) { src = wv; dst = hw + 2 * DIM * DIM; n4 = DIM * DIM / 4; }
    else { src = wo; dst = hw + 3 * DIM * DIM; n4 = DIM * DIM / 4; }
    int i = blockIdx.x * blockDim.x + threadIdx.x;
    int stride = gridDim.x * blockDim.x;
    for (; i < n4; i += stride) {
        float4 v = ((const float4*)src)[i];
        ((__half2*)dst)[2 * i] = __floats2half2_rn(v.x, v.y);
        ((__half2*)dst)[2 * i + 1] = __floats2half2_rn(v.z, v.w);
    }
}

// ---------------------------------------------------------------------------
// GEMM: Y[m][n] = sum_k X[m][k]*W[n][k] (x @ W.T), fp16 m16n8k16, f32 accum,
// ldmatrix fragment loads, 2-stage cp.async. Block 128x128, 256 thr = 8 warps.
// ---------------------------------------------------------------------------
#define PADH 72                               // halves per row (36 words)
#define GST_H (2 * 128 * PADH)
#define GEMM_SMEM (2 * GST_H * 2)             // 73728 B

__device__ __forceinline__ void gemm_body(const __half* __restrict__ X,
                                          const __half* __restrict__ W,
                                          __half* __restrict__ Yh,
                                          float* __restrict__ Yf) {
    extern __shared__ __half smg[];
    const int tid = threadIdx.x, lane = tid & 31, wid = tid >> 5;
    const int wm = wid & 3, wn = wid >> 2;
    const int mb = blockIdx.y * 128, nb = blockIdx.x * 128;
    const int lr = lane >> 2, lc = lane & 3;
    const uint32_t sb = smem_u32(smg);

    // ldmatrix lane address components
    const int arow = (lane & 7) + ((lane >> 3) & 1) * 8;  // A/Q row-in-16
    const int acol = (lane >> 4) * 8;                     // A col half-sel
    const int brow = (lane & 7) + (lane >> 4) * 8;        // B row-in-16
    const int bcol = ((lane >> 3) & 1) * 8;               // B col half-sel

    uint32_t a_off[2], b_off[4];
#pragma unroll
    for (int mt = 0; mt < 2; mt++)
        a_off[mt] = (uint32_t)((wm * 32 + mt * 16 + arow) * PADH + acol) * 2;
#pragma unroll
    for (int p = 0; p < 4; p++)
        b_off[p] = (uint32_t)(128 * PADH + (wn * 64 + p * 16 + brow) * PADH + bcol) * 2;

    float acc[2][8][4];
#pragma unroll
    for (int i = 0; i < 2; i++)
#pragma unroll
        for (int j = 0; j < 8; j++)
#pragma unroll
            for (int c = 0; c < 4; c++) acc[i][j][c] = 0.0f;

    const int cr = tid >> 3, cc = tid & 7;
    auto issue = [&](int kt, int s) {
        const int k0 = kt * 64;
        uint32_t base = sb + (uint32_t)s * GST_H * 2;
#pragma unroll
        for (int t = 0; t < 8; t++) {
            int r = cr + (t >> 1) * 32;
            const __half* src = (t & 1) ? W + (size_t)(nb + r) * DIM + k0 + cc * 8
                                        : X + (size_t)(mb + r) * DIM + k0 + cc * 8;
            uint32_t dst = base + ((t & 1) ? (uint32_t)(128 * PADH * 2) : 0u) +
                           (uint32_t)(r * PADH + cc * 8) * 2;
            CP16(dst, src);
        }
        CP_COMMIT();
    };

    issue(0, 0);
    for (int kt = 0; kt < 8; kt++) {
        if (kt < 7) { issue(kt + 1, (kt + 1) & 1); CP_WAIT1(); }
        else CP_WAIT0();
        __syncthreads();

        const uint32_t sbs = sb + ((kt & 1) ? (uint32_t)GST_H * 2 : 0u);
#pragma unroll
        for (int ks = 0; ks < 4; ks++) {
            const uint32_t kkb = (uint32_t)(ks * 16) * 2;
            uint32_t a[2][4], b[8][2];
#pragma unroll
            for (int mt = 0; mt < 2; mt++)
                LDSM4(a[mt][0], a[mt][1], a[mt][2], a[mt][3],
                      sbs + a_off[mt] + kkb);
#pragma unroll
            for (int p = 0; p < 4; p++)
                LDSM4(b[2 * p][0], b[2 * p][1], b[2 * p + 1][0], b[2 * p + 1][1],
                      sbs + b_off[p] + kkb);
#pragma unroll
            for (int mt = 0; mt < 2; mt++)
#pragma unroll
                for (int nt = 0; nt < 8; nt++)
                    mma_f16(acc[mt][nt], a[mt], b[nt]);
        }
        __syncthreads();
    }

#pragma unroll
    for (int mt = 0; mt < 2; mt++) {
        int r0 = mb + wm * 32 + mt * 16 + lr;
#pragma unroll
        for (int nt = 0; nt < 8; nt++) {
            int c0 = nb + wn * 64 + nt * 8 + 2 * lc;
            if (Yf) {
                *(float2*)(Yf + (size_t)r0 * DIM + c0) =
                    make_float2(acc[mt][nt][0], acc[mt][nt][1]);
                *(float2*)(Yf + (size_t)(r0 + 8) * DIM + c0) =
                    make_float2(acc[mt][nt][2], acc[mt][nt][3]);
            } else {
                *(uint32_t*)(Yh + (size_t)r0 * DIM + c0) =
                    pack2(acc[mt][nt][0], acc[mt][nt][1]);
                *(uint32_t*)(Yh + (size_t)(r0 + 8) * DIM + c0) =
                    pack2(acc[mt][nt][2], acc[mt][nt][3]);
            }
        }
    }
}

__global__ __launch_bounds__(256, 2) void qkv_gemm() {
    const int z = blockIdx.z;
    __half* Y = (z == 0) ? g_q : (z == 1) ? g_k : g_v;
    gemm_body(hx, hw + (size_t)z * DIM * DIM, Y, nullptr);
}

__global__ __launch_bounds__(256, 2) void out_gemm(float* __restrict__ out) {
    gemm_body(g_o, hw + 3 * (size_t)DIM * DIM, nullptr, out);
}

// ---------------------------------------------------------------------------
// Flash attention, fp16 m16n8k16, ldmatrix (trans for V), single-pass softmax,
// P packed into A fragments, key-split warp pairs, 2-stage cp.async.
// 512 thr = 16 warps: wq=wid>>1 owns q rows [wq*16,+16); wk=wid&1 owns keys
// [wk*32,+32) per 64-key tile.
// ---------------------------------------------------------------------------
#define PADA 72
#define KS_H (64 * PADA)
#define ASTAGE_H (2 * KS_H)
#define ATTN_SMEM (2 * ASTAGE_H * 2)          // 36864 B

__global__ __launch_bounds__(512, 1) void attn_f16() {
    extern __shared__ __half smh[];
    const int tid = threadIdx.x, lane = tid & 31, wid = tid >> 5;
    const int lr = lane >> 2, lc = lane & 3;
    const int wq_ = wid >> 1, wk_ = wid & 1;
    const int bh = blockIdx.y, b_ = bh >> 3, h_ = bh & 7;
    const int q0 = blockIdx.x * 128;
    const uint32_t sb = smem_u32(smh);

    const __half* Qg = g_q + (size_t)b_ * L * DIM + h_ * 64;
    const __half* Kg = g_k + (size_t)b_ * L * DIM + h_ * 64;
    const __half* Vg = g_v + (size_t)b_ * L * DIM + h_ * 64;

    // ldmatrix address components
    const int arow = (lane & 7) + ((lane >> 3) & 1) * 8;
    const int acol = (lane >> 4) * 8;
    const int brow = (lane & 7) + (lane >> 4) * 8;
    const int bcol = ((lane >> 3) & 1) * 8;

    // K fragment offsets (p=0: keys 0..15, p=1: keys 16..31 of warp's half)
    uint32_t k_off[2];
#pragma unroll
    for (int p = 0; p < 2; p++)
        k_off[p] = (uint32_t)((wk_ * 32 + p * 16 + brow) * PADA + bcol) * 2;
    // V fragment (trans): row = key, col = d
    const uint32_t v_roff = (uint32_t)(arow * PADA) * 2;   // + kkv*PADA + dsel

    // cp.async one K/V tile: 2 CP16 per thread.
    const int ar = tid >> 3, ac = tid & 7;
    auto issue = [&](int t, int s) {
        const int k0g = t * 64;
        uint32_t base = sb + (uint32_t)s * ASTAGE_H * 2;
        CP16(base + (uint32_t)(ar * PADA + ac * 8) * 2,
             Kg + (size_t)(k0g + ar) * DIM + ac * 8);
        CP16(base + (uint32_t)(KS_H + ar * PADA + ac * 8) * 2,
             Vg + (size_t)(k0g + ar) * DIM + ac * 8);
        CP_COMMIT();
    };

    issue(0, 0);                              // tile0 -> stage0

    // Stage Q into stage1, extract A fragments via ldmatrix.
    __half* Qs = smh + ASTAGE_H;
#pragma unroll
    for (int t = 0; t < 2; t++) {
        int idx = tid + t * 512;
        int r = idx >> 3, c = idx & 7;
        *(uint4*)&Qs[r * PADA + c * 8] =
            *(const uint4*)(Qg + (size_t)(q0 + r) * DIM + c * 8);
    }
    __syncthreads();
    uint32_t aq[4][4];
    {
        uint32_t qbase = sb + (uint32_t)ASTAGE_H * 2 +
                         (uint32_t)((wq_ * 16 + arow) * PADA + acol) * 2;
#pragma unroll
        for (int ks = 0; ks < 4; ks++)
            LDSM4(aq[ks][0], aq[ks][1], aq[ks][2], aq[ks][3],
                  qbase + (uint32_t)(ks * 16) * 2);
    }
    __syncthreads();                          // stage1 free for tile1

    float o[8][4];
#pragma unroll
    for (int nt = 0; nt < 8; nt++)
#pragma unroll
        for (int c = 0; c < 4; c++) o[nt][c] = 0.0f;
    float l0 = 0.0f, l1 = 0.0f;

    const int row0 = q0 + wq_ * 16 + lr;
    const int row1 = row0 + 8;

    for (int t = 0; t < 32; t++) {
        if (t < 31) { issue(t + 1, (t + 1) & 1); CP_WAIT1(); }
        else CP_WAIT0();
        __syncthreads();

        const uint32_t sbs = sb + ((t & 1) ? (uint32_t)ASTAGE_H * 2 : 0u);
        const int k0g = t * 64;

        // S = Q @ K^T : 16 q x 32 keys per warp.
        float s[4][4];
#pragma unroll
        for (int nt = 0; nt < 4; nt++)
#pragma unroll
            for (int c = 0; c < 4; c++) s[nt][c] = 0.0f;
#pragma unroll
        for (int ks = 0; ks < 4; ks++) {
            const uint32_t kkb = (uint32_t)(ks * 16) * 2;
            uint32_t bk[4][2];
#pragma unroll
            for (int p = 0; p < 2; p++)
                LDSM4(bk[2 * p][0], bk[2 * p][1], bk[2 * p + 1][0], bk[2 * p + 1][1],
                      sbs + k_off[p] + kkb);
#pragma unroll
            for (int nt = 0; nt < 4; nt++) mma_f16(s[nt], aq[ks], bk[nt]);
        }

        // p = exp(s*SCALE); diagonal -> 0; row sums.
#pragma unroll
        for (int nt = 0; nt < 4; nt++) {
            int key = k0g + wk_ * 32 + nt * 8 + 2 * lc;
            float p0 = __expf(s[nt][0] * SCALE);
            float p1 = __expf(s[nt][1] * SCALE);
            float p2 = __expf(s[nt][2] * SCALE);
            float p3 = __expf(s[nt][3] * SCALE);
            if (key == row0) p0 = 0.0f;
            if (key + 1 == row0) p1 = 0.0f;
            if (key == row1) p2 = 0.0f;
            if (key + 1 == row1) p3 = 0.0f;
            l0 += p0 + p1;
            l1 += p2 + p3;
            s[nt][0] = p0; s[nt][1] = p1; s[nt][2] = p2; s[nt][3] = p3;
        }

        // O += P @ V.  P -> A regs (fp16 C layout == A layout); V via ldmatrix.trans.
#pragma unroll
        for (int ksl = 0; ksl < 2; ksl++) {
            uint32_t ap[4];
            ap[0] = pack2(s[2 * ksl][0], s[2 * ksl][1]);
            ap[1] = pack2(s[2 * ksl][2], s[2 * ksl][3]);
            ap[2] = pack2(s[2 * ksl + 1][0], s[2 * ksl + 1][1]);
            ap[3] = pack2(s[2 * ksl + 1][2], s[2 * ksl + 1][3]);

            const int kkv = wk_ * 32 + ksl * 16;
            uint32_t vbase = sbs + (uint32_t)KS_H * 2 +
                             (uint32_t)(kkv * PADA) * 2 + v_roff +
                             (uint32_t)acol * 2;
            uint32_t bv[8][2];
#pragma unroll
            for (int p = 0; p < 4; p++)
                LDSM4T(bv[2 * p][0], bv[2 * p][1], bv[2 * p + 1][0], bv[2 * p + 1][1],
                       vbase + (uint32_t)(p * 16) * 2);
#pragma unroll
            for (int nt = 0; nt < 8; nt++) mma_f16(o[nt], ap, bv[nt]);
        }
        __syncthreads();
    }

    // Merge key-half pairs via smem.
    float* OS = (float*)smh;                  // [8][32][32]
    float* LS = (float*)smh + 8 * 32 * 32;    // [8][32][2]
    if (wk_ == 1) {
        float* dst = OS + ((size_t)wq_ * 32 + lane) * 32;
#pragma unroll
        for (int nt = 0; nt < 8; nt++)
#pragma unroll
            for (int c = 0; c < 4; c++) dst[nt * 4 + c] = o[nt][c];
        LS[(wq_ * 32 + lane) * 2 + 0] = l0;
        LS[(wq_ * 32 + lane) * 2 + 1] = l1;
    }
    __syncthreads();
    if (wk_ == 0) {
        const float* srcp = OS + ((size_t)wq_ * 32 + lane) * 32;
#pragma unroll
        for (int nt = 0; nt < 8; nt++)
#pragma unroll
            for (int c = 0; c < 4; c++) o[nt][c] += srcp[nt * 4 + c];
        l0 += LS[(wq_ * 32 + lane) * 2 + 0];
        l1 += LS[(wq_ * 32 + lane) * 2 + 1];
#pragma unroll
        for (int off = 1; off <= 2; off <<= 1) {
            l0 += __shfl_xor_sync(0xffffffffu, l0, off);
            l1 += __shfl_xor_sync(0xffffffffu, l1, off);
        }
        const float inv0 = 1.0f / l0, inv1 = 1.0f / l1;
        __half* Og = g_o + ((size_t)b_ * L) * DIM + h_ * 64;
#pragma unroll
        for (int nt = 0; nt < 8; nt++) {
            int c0 = nt * 8 + 2 * lc;
            *(uint32_t*)(Og + (size_t)row0 * DIM + c0) =
                pack2(o[nt][0] * inv0, o[nt][1] * inv0);
            *(uint32_t*)(Og + (size_t)row1 * DIM + c0) =
                pack2(o[nt][2] * inv1, o[nt][3] * inv1);
        }
    }
}

// ---------------------------------------------------------------------------
extern "C" void kernel_launch(void* const* d_in, const int* in_sizes, int n_in,
                              void* d_out, int out_size) {
    const float* x  = (const float*)d_in[0];
    const float* wq = (const float*)d_in[1];
    const float* wk = (const float*)d_in[2];
    const float* wv = (const float*)d_in[3];
    const float* wo = (const float*)d_in[4];
    float* out = (float*)d_out;

    cudaFuncSetAttribute(qkv_gemm, cudaFuncAttributeMaxDynamicSharedMemorySize,
                         GEMM_SMEM);
    cudaFuncSetAttribute(out_gemm, cudaFuncAttributeMaxDynamicSharedMemorySize,
                         GEMM_SMEM);
    cudaFuncSetAttribute(attn_f16, cudaFuncAttributeMaxDynamicSharedMemorySize,
                         ATTN_SMEM);

    cvt_all<<<dim3(128, 5), 256>>>(x, wq, wk, wv, wo);
    qkv_gemm<<<dim3(4, 64, 3), 256, GEMM_SMEM>>>();
    attn_f16<<<dim3(L / 128, B * H), 512, ATTN_SMEM>>>();
    out_gemm<<<dim3(4, 64), 256, GEMM_SMEM>>>(out);
}

// round 9
// speedup vs baseline: 2.2634x; 1.0361x over previous
#include <cuda_runtime.h>
#include <cuda_fp16.h>
#include <cstdint>

#define B 4
#define L 2048
#define DIM 512
#define H 8
#define D 64
#define M_TOTAL (B * L)
#define SCALE 0.125f

// fp16 scratch (allocation-free rule: __device__ globals).
__device__ __half hx[M_TOTAL * DIM];
__device__ __half hw[4 * DIM * DIM];         // wq, wk, wv, wo
__device__ __half g_q[M_TOTAL * DIM];
__device__ __half g_k[M_TOTAL * DIM];
__device__ __half g_v[M_TOTAL * DIM];
__device__ __half g_o[M_TOTAL * DIM];

__device__ __forceinline__ uint32_t pack2(float a, float b) {
    __half2 h = __floats2half2_rn(a, b);
    return *(uint32_t*)&h;
}

__device__ __forceinline__ void mma_f16(float* d, const uint32_t* a,
                                        const uint32_t* b) {
    asm volatile(
        "mma.sync.aligned.m16n8k16.row.col.f32.f16.f16.f32 "
        "{%0,%1,%2,%3}, {%4,%5,%6,%7}, {%8,%9}, {%0,%1,%2,%3};"
        : "+f"(d[0]), "+f"(d[1]), "+f"(d[2]), "+f"(d[3])
        : "r"(a[0]), "r"(a[1]), "r"(a[2]), "r"(a[3]), "r"(b[0]), "r"(b[1]));
}

__device__ __forceinline__ uint32_t smem_u32(const void* p) {
    uint32_t a;
    asm("{ .reg .u64 t; cvta.to.shared.u64 t, %1; cvt.u32.u64 %0, t; }"
        : "=r"(a) : "l"(p));
    return a;
}

#define LDSM4(d0, d1, d2, d3, a) \
    asm volatile("ldmatrix.sync.aligned.m8n8.x4.shared.b16 {%0,%1,%2,%3}, [%4];" \
                 : "=r"(d0), "=r"(d1), "=r"(d2), "=r"(d3) : "r"(a))
#define LDSM4T(d0, d1, d2, d3, a) \
    asm volatile("ldmatrix.sync.aligned.m8n8.x4.trans.shared.b16 {%0,%1,%2,%3}, [%4];" \
                 : "=r"(d0), "=r"(d1), "=r"(d2), "=r"(d3) : "r"(a))
#define LDSM2T(d0, d1, a) \
    asm volatile("ldmatrix.sync.aligned.m8n8.x2.trans.shared.b16 {%0,%1}, [%2];" \
                 : "=r"(d0), "=r"(d1) : "r"(a))

#define CP16(dst, src) \
    asm volatile("cp.async.cg.shared.global [%0], [%1], 16;" \
                 :: "r"(dst), "l"(src) : "memory")
#define CP_COMMIT() asm volatile("cp.async.commit_group;" ::: "memory")
#define CP_WAIT1() asm volatile("cp.async.wait_group 1;" ::: "memory")
#define CP_WAIT0() asm volatile("cp.async.wait_group 0;" ::: "memory")

// ---------------------------------------------------------------------------
// fp32 -> fp16 conversion, one launch (blockIdx.y selects tensor).
// ---------------------------------------------------------------------------
__global__ void cvt_all(const float* __restrict__ x,  const float* __restrict__ wq,
                        const float* __restrict__ wk, const float* __restrict__ wv,
                        const float* __restrict__ wo) {
    const int sel = blockIdx.y;
    const float* src;
    __half* dst;
    int n4;
    if (sel == 0) { src = x;  dst = hx;                 n4 = M_TOTAL * DIM / 4; }
    else if (sel == 1) { src = wq; dst = hw;                n4 = DIM * DIM / 4; }
    else if (sel == 2) { src = wk; dst = hw + DIM * DIM;    n4 = DIM * DIM / 4; }
    else if (sel == 3) { src = wv; dst = hw + 2 * DIM * DIM; n4 = DIM * DIM / 4; }
    else { src = wo; dst = hw + 3 * DIM * DIM; n4 = DIM * DIM / 4; }
    int i = blockIdx.x * blockDim.x + threadIdx.x;
    int stride = gridDim.x * blockDim.x;
    for (; i < n4; i += stride) {
        float4 v = ((const float4*)src)[i];
        ((__half2*)dst)[2 * i] = __floats2half2_rn(v.x, v.y);
        ((__half2*)dst)[2 * i + 1] = __floats2half2_rn(v.z, v.w);
    }
}

// ---------------------------------------------------------------------------
// GEMM: Y[m][n] = sum_k X[m][k]*W[n][k] (x @ W.T), fp16 m16n8k16, f32 accum,
// ldmatrix fragment loads, 2-stage cp.async. Block 128x128, 256 thr = 8 warps.
// ---------------------------------------------------------------------------
#define PADH 72
#define GST_H (2 * 128 * PADH)
#define GEMM_SMEM (2 * GST_H * 2)             // 73728 B

__device__ __forceinline__ void gemm_body(const __half* __restrict__ X,
                                          const __half* __restrict__ W,
                                          __half* __restrict__ Yh,
                                          float* __restrict__ Yf) {
    extern __shared__ __half smg[];
    const int tid = threadIdx.x, lane = tid & 31, wid = tid >> 5;
    const int wm = wid & 3, wn = wid >> 2;
    const int mb = blockIdx.y * 128, nb = blockIdx.x * 128;
    const int lr = lane >> 2, lc = lane & 3;
    const uint32_t sb = smem_u32(smg);

    const int arow = (lane & 7) + ((lane >> 3) & 1) * 8;
    const int acol = (lane >> 4) * 8;
    const int brow = (lane & 7) + (lane >> 4) * 8;
    const int bcol = ((lane >> 3) & 1) * 8;

    uint32_t a_off[2], b_off[4];
#pragma unroll
    for (int mt = 0; mt < 2; mt++)
        a_off[mt] = (uint32_t)((wm * 32 + mt * 16 + arow) * PADH + acol) * 2;
#pragma unroll
    for (int p = 0; p < 4; p++)
        b_off[p] = (uint32_t)(128 * PADH + (wn * 64 + p * 16 + brow) * PADH + bcol) * 2;

    float acc[2][8][4];
#pragma unroll
    for (int i = 0; i < 2; i++)
#pragma unroll
        for (int j = 0; j < 8; j++)
#pragma unroll
            for (int c = 0; c < 4; c++) acc[i][j][c] = 0.0f;

    const int cr = tid >> 3, cc = tid & 7;
    auto issue = [&](int kt, int s) {
        const int k0 = kt * 64;
        uint32_t base = sb + (uint32_t)s * GST_H * 2;
#pragma unroll
        for (int t = 0; t < 8; t++) {
            int r = cr + (t >> 1) * 32;
            const __half* src = (t & 1) ? W + (size_t)(nb + r) * DIM + k0 + cc * 8
                                        : X + (size_t)(mb + r) * DIM + k0 + cc * 8;
            uint32_t dst = base + ((t & 1) ? (uint32_t)(128 * PADH * 2) : 0u) +
                           (uint32_t)(r * PADH + cc * 8) * 2;
            CP16(dst, src);
        }
        CP_COMMIT();
    };

    issue(0, 0);
    for (int kt = 0; kt < 8; kt++) {
        if (kt < 7) { issue(kt + 1, (kt + 1) & 1); CP_WAIT1(); }
        else CP_WAIT0();
        __syncthreads();

        const uint32_t sbs = sb + ((kt & 1) ? (uint32_t)GST_H * 2 : 0u);
#pragma unroll
        for (int ks = 0; ks < 4; ks++) {
            const uint32_t kkb = (uint32_t)(ks * 16) * 2;
            uint32_t a[2][4], b[8][2];
#pragma unroll
            for (int mt = 0; mt < 2; mt++)
                LDSM4(a[mt][0], a[mt][1], a[mt][2], a[mt][3],
                      sbs + a_off[mt] + kkb);
#pragma unroll
            for (int p = 0; p < 4; p++)
                LDSM4(b[2 * p][0], b[2 * p][1], b[2 * p + 1][0], b[2 * p + 1][1],
                      sbs + b_off[p] + kkb);
#pragma unroll
            for (int mt = 0; mt < 2; mt++)
#pragma unroll
                for (int nt = 0; nt < 8; nt++)
                    mma_f16(acc[mt][nt], a[mt], b[nt]);
        }
        __syncthreads();
    }

#pragma unroll
    for (int mt = 0; mt < 2; mt++) {
        int r0 = mb + wm * 32 + mt * 16 + lr;
#pragma unroll
        for (int nt = 0; nt < 8; nt++) {
            int c0 = nb + wn * 64 + nt * 8 + 2 * lc;
            if (Yf) {
                *(float2*)(Yf + (size_t)r0 * DIM + c0) =
                    make_float2(acc[mt][nt][0], acc[mt][nt][1]);
                *(float2*)(Yf + (size_t)(r0 + 8) * DIM + c0) =
                    make_float2(acc[mt][nt][2], acc[mt][nt][3]);
            } else {
                *(uint32_t*)(Yh + (size_t)r0 * DIM + c0) =
                    pack2(acc[mt][nt][0], acc[mt][nt][1]);
                *(uint32_t*)(Yh + (size_t)(r0 + 8) * DIM + c0) =
                    pack2(acc[mt][nt][2], acc[mt][nt][3]);
            }
        }
    }
}

__global__ __launch_bounds__(256, 2) void qkv_gemm() {
    const int z = blockIdx.z;
    __half* Y = (z == 0) ? g_q : (z == 1) ? g_k : g_v;
    gemm_body(hx, hw + (size_t)z * DIM * DIM, Y, nullptr);
}

__global__ __launch_bounds__(256, 2) void out_gemm(float* __restrict__ out) {
    gemm_body(g_o, hw + 3 * (size_t)DIM * DIM, nullptr, out);
}

// ---------------------------------------------------------------------------
// Flash attention, fp16 m16n8k16, 128-key stages (2 sub-tiles, no barrier
// between), Q pre-scaled by SCALE, l via ones-column mma, ldmatrix loads.
// 512 thr = 16 warps: wq=wid>>1 owns q rows [wq*16,+16); wk=wid&1 owns keys
// [wk*32,+32) of each 64-key sub-tile.
// ---------------------------------------------------------------------------
#define PADA 72
#define KS_H (128 * PADA)                     // K halves per stage (9216)
#define ASTAGE_H (2 * KS_H)                   // K + V per stage
#define ATTN_SMEM (2 * ASTAGE_H * 2)          // 73728 B

__global__ __launch_bounds__(512, 1) void attn_f16() {
    extern __shared__ __half smh[];
    const int tid = threadIdx.x, lane = tid & 31, wid = tid >> 5;
    const int lr = lane >> 2, lc = lane & 3;
    const int wq_ = wid >> 1, wk_ = wid & 1;
    const int bh = blockIdx.y, b_ = bh >> 3, h_ = bh & 7;
    const int q0 = blockIdx.x * 128;
    const uint32_t sb = smem_u32(smh);

    const __half* Qg = g_q + (size_t)b_ * L * DIM + h_ * 64;
    const __half* Kg = g_k + (size_t)b_ * L * DIM + h_ * 64;
    const __half* Vg = g_v + (size_t)b_ * L * DIM + h_ * 64;

    const int arow = (lane & 7) + ((lane >> 3) & 1) * 8;
    const int acol = (lane >> 4) * 8;
    const int brow = (lane & 7) + (lane >> 4) * 8;
    const int bcol = ((lane >> 3) & 1) * 8;

    uint32_t k_off[2];
#pragma unroll
    for (int p = 0; p < 2; p++)
        k_off[p] = (uint32_t)((wk_ * 32 + p * 16 + brow) * PADA + bcol) * 2;
    const uint32_t v_roff = (uint32_t)(arow * PADA) * 2;
    const uint32_t v_l_off = (uint32_t)((lane & 15) * PADA + 64) * 2;

    // cp.async one 128-key K/V stage: 4 CP16 per thread.
    auto issue = [&](int t, int s) {
        const int k0g = t * 128;
        uint32_t base = sb + (uint32_t)s * ASTAGE_H * 2;
#pragma unroll
        for (int u = 0; u < 2; u++) {
            int idx = tid + u * 512;          // 0..1023
            int r = idx >> 3, c = idx & 7;
            CP16(base + (uint32_t)(r * PADA + c * 8) * 2,
                 Kg + (size_t)(k0g + r) * DIM + c * 8);
            CP16(base + (uint32_t)(KS_H + r * PADA + c * 8) * 2,
                 Vg + (size_t)(k0g + r) * DIM + c * 8);
        }
        CP_COMMIT();
    };

    issue(0, 0);                              // stage0 <- keys 0..127

    // Stage Q (scaled by SCALE, exact in fp16) into stage1 K region.
    __half* Qs = smh + ASTAGE_H;
    {
        const __half2 sc = __half2half2(__float2half(SCALE));
#pragma unroll
        for (int t = 0; t < 2; t++) {
            int idx = tid + t * 512;
            int r = idx >> 3, c = idx & 7;
            uint4 q4 = *(const uint4*)(Qg + (size_t)(q0 + r) * DIM + c * 8);
            __half2* qh = (__half2*)&q4;
#pragma unroll
            for (int j = 0; j < 4; j++) qh[j] = __hmul2(qh[j], sc);
            *(uint4*)&Qs[r * PADA + c * 8] = q4;
        }
    }
    // Ones-column init in V padding (both stages): col 64 = 1, 65..71 = 0.
    if (tid < 256) {
        int s_ = tid >> 7, r = tid & 127;
        __half* p = smh + s_ * ASTAGE_H + KS_H + r * PADA + 64;
        *(uint4*)p = make_uint4(0x00003C00u, 0u, 0u, 0u);
    }
    __syncthreads();
    uint32_t aq[4][4];
    {
        uint32_t qbase = sb + (uint32_t)ASTAGE_H * 2 +
                         (uint32_t)((wq_ * 16 + arow) * PADA + acol) * 2;
#pragma unroll
        for (int ks = 0; ks < 4; ks++)
            LDSM4(aq[ks][0], aq[ks][1], aq[ks][2], aq[ks][3],
                  qbase + (uint32_t)(ks * 16) * 2);
    }
    __syncthreads();                          // stage1 K region free for tile1

    float o[8][4], o_l[4];
#pragma unroll
    for (int nt = 0; nt < 8; nt++)
#pragma unroll
        for (int c = 0; c < 4; c++) o[nt][c] = 0.0f;
#pragma unroll
    for (int c = 0; c < 4; c++) o_l[c] = 0.0f;

    const int row0 = q0 + wq_ * 16 + lr;
    const int row1 = row0 + 8;

    for (int t = 0; t < 16; t++) {
        if (t < 15) { issue(t + 1, (t + 1) & 1); CP_WAIT1(); }
        else CP_WAIT0();
        __syncthreads();

        const uint32_t sbs = sb + ((t & 1) ? (uint32_t)ASTAGE_H * 2 : 0u);

#pragma unroll
        for (int half = 0; half < 2; half++) {
            const uint32_t hoff = (uint32_t)(half * 64 * PADA) * 2;
            const int k0g = t * 128 + half * 64;

            // S = Q @ K^T : 16 q x 32 keys.
            float s[4][4];
#pragma unroll
            for (int nt = 0; nt < 4; nt++)
#pragma unroll
                for (int c = 0; c < 4; c++) s[nt][c] = 0.0f;
#pragma unroll
            for (int ks = 0; ks < 4; ks++) {
                const uint32_t kkb = (uint32_t)(ks * 16) * 2;
                uint32_t bk[4][2];
#pragma unroll
                for (int p = 0; p < 2; p++)
                    LDSM4(bk[2 * p][0], bk[2 * p][1],
                          bk[2 * p + 1][0], bk[2 * p + 1][1],
                          sbs + hoff + k_off[p] + kkb);
#pragma unroll
                for (int nt = 0; nt < 4; nt++) mma_f16(s[nt], aq[ks], bk[nt]);
            }

            // p = exp(s) (Q was pre-scaled); diagonal -> 0.
#pragma unroll
            for (int nt = 0; nt < 4; nt++) {
                int key = k0g + wk_ * 32 + nt * 8 + 2 * lc;
                float p0 = __expf(s[nt][0]);
                float p1 = __expf(s[nt][1]);
                float p2 = __expf(s[nt][2]);
                float p3 = __expf(s[nt][3]);
                if (key == row0) p0 = 0.0f;
                if (key + 1 == row0) p1 = 0.0f;
                if (key == row1) p2 = 0.0f;
                if (key + 1 == row1) p3 = 0.0f;
                s[nt][0] = p0; s[nt][1] = p1; s[nt][2] = p2; s[nt][3] = p3;
            }

            // O += P @ V; l += P @ ones (V pad column).
#pragma unroll
            for (int ksl = 0; ksl < 2; ksl++) {
                uint32_t ap[4];
                ap[0] = pack2(s[2 * ksl][0], s[2 * ksl][1]);
                ap[1] = pack2(s[2 * ksl][2], s[2 * ksl][3]);
                ap[2] = pack2(s[2 * ksl + 1][0], s[2 * ksl + 1][1]);
                ap[3] = pack2(s[2 * ksl + 1][2], s[2 * ksl + 1][3]);

                const int kkv = wk_ * 32 + ksl * 16;
                const uint32_t vb = sbs + (uint32_t)KS_H * 2 + hoff +
                                    (uint32_t)(kkv * PADA) * 2;
                uint32_t bv[8][2];
#pragma unroll
                for (int p = 0; p < 4; p++)
                    LDSM4T(bv[2 * p][0], bv[2 * p][1],
                           bv[2 * p + 1][0], bv[2 * p + 1][1],
                           vb + v_roff + (uint32_t)acol * 2 +
                           (uint32_t)(p * 16) * 2);
#pragma unroll
                for (int nt = 0; nt < 8; nt++) mma_f16(o[nt], ap, bv[nt]);

                uint32_t bl[2];
                LDSM2T(bl[0], bl[1], vb + v_l_off);
                mma_f16(o_l, ap, bl);
            }
        }
        __syncthreads();
    }

    // Merge key-half pairs via smem: o (32) + o_l (4) per thread.
    float* OS = (float*)smh;                  // [8][32][36]
    if (wk_ == 1) {
        float* dst = OS + ((size_t)wq_ * 32 + lane) * 36;
#pragma unroll
        for (int nt = 0; nt < 8; nt++)
#pragma unroll
            for (int c = 0; c < 4; c++) dst[nt * 4 + c] = o[nt][c];
#pragma unroll
        for (int c = 0; c < 4; c++) dst[32 + c] = o_l[c];
    }
    __syncthreads();
    if (wk_ == 0) {
        const float* srcp = OS + ((size_t)wq_ * 32 + lane) * 36;
#pragma unroll
        for (int nt = 0; nt < 8; nt++)
#pragma unroll
            for (int c = 0; c < 4; c++) o[nt][c] += srcp[nt * 4 + c];
#pragma unroll
        for (int c = 0; c < 4; c++) o_l[c] += srcp[32 + c];

        // l lives in col 64 -> lc==0 lanes; broadcast within quad.
        float l0 = __shfl_sync(0xffffffffu, o_l[0], lane & 28);
        float l1 = __shfl_sync(0xffffffffu, o_l[2], lane & 28);
        const float inv0 = 1.0f / l0, inv1 = 1.0f / l1;
        __half* Og = g_o + ((size_t)b_ * L) * DIM + h_ * 64;
#pragma unroll
        for (int nt = 0; nt < 8; nt++) {
            int c0 = nt * 8 + 2 * lc;
            *(uint32_t*)(Og + (size_t)row0 * DIM + c0) =
                pack2(o[nt][0] * inv0, o[nt][1] * inv0);
            *(uint32_t*)(Og + (size_t)row1 * DIM + c0) =
                pack2(o[nt][2] * inv1, o[nt][3] * inv1);
        }
    }
}

// ---------------------------------------------------------------------------
extern "C" void kernel_launch(void* const* d_in, const int* in_sizes, int n_in,
                              void* d_out, int out_size) {
    const float* x  = (const float*)d_in[0];
    const float* wq = (const float*)d_in[1];
    const float* wk = (const float*)d_in[2];
    const float* wv = (const float*)d_in[3];
    const float* wo = (const float*)d_in[4];
    float* out = (float*)d_out;

    cudaFuncSetAttribute(qkv_gemm, cudaFuncAttributeMaxDynamicSharedMemorySize,
                         GEMM_SMEM);
    cudaFuncSetAttribute(out_gemm, cudaFuncAttributeMaxDynamicSharedMemorySize,
                         GEMM_SMEM);
    cudaFuncSetAttribute(attn_f16, cudaFuncAttributeMaxDynamicSharedMemorySize,
                         ATTN_SMEM);

    cvt_all<<<dim3(128, 5), 256>>>(x, wq, wk, wv, wo);
    qkv_gemm<<<dim3(4, 64, 3), 256, GEMM_SMEM>>>();
    attn_f16<<<dim3(L / 128, B * H), 512, ATTN_SMEM>>>();
    out_gemm<<<dim3(4, 64), 256, GEMM_SMEM>>>(out);
}

// round 10
// speedup vs baseline: 2.4580x; 1.0860x over previous
#include <cuda_runtime.h>
#include <cuda_fp16.h>
#include <cstdint>

#define B 4
#define L 2048
#define DIM 512
#define H 8
#define D 64
#define M_TOTAL (B * L)
#define SCALE 0.125f

// fp16 scratch (allocation-free rule: __device__ globals).
__device__ __half hx[M_TOTAL * DIM];
__device__ __half hw[4 * DIM * DIM];         // wq, wk, wv, wo
__device__ __half g_q[M_TOTAL * DIM];
__device__ __half g_k[M_TOTAL * DIM];
__device__ __half g_v[M_TOTAL * DIM];
__device__ __half g_o[M_TOTAL * DIM];

__device__ __forceinline__ uint32_t pack2(float a, float b) {
    __half2 h = __floats2half2_rn(a, b);
    return *(uint32_t*)&h;
}

__device__ __forceinline__ void mma_f16(float* d, const uint32_t* a,
                                        const uint32_t* b) {
    asm volatile(
        "mma.sync.aligned.m16n8k16.row.col.f32.f16.f16.f32 "
        "{%0,%1,%2,%3}, {%4,%5,%6,%7}, {%8,%9}, {%0,%1,%2,%3};"
        : "+f"(d[0]), "+f"(d[1]), "+f"(d[2]), "+f"(d[3])
        : "r"(a[0]), "r"(a[1]), "r"(a[2]), "r"(a[3]), "r"(b[0]), "r"(b[1]));
}

__device__ __forceinline__ uint32_t smem_u32(const void* p) {
    uint32_t a;
    asm("{ .reg .u64 t; cvta.to.shared.u64 t, %1; cvt.u32.u64 %0, t; }"
        : "=r"(a) : "l"(p));
    return a;
}

#define LDSM4(d0, d1, d2, d3, a) \
    asm volatile("ldmatrix.sync.aligned.m8n8.x4.shared.b16 {%0,%1,%2,%3}, [%4];" \
                 : "=r"(d0), "=r"(d1), "=r"(d2), "=r"(d3) : "r"(a))
#define LDSM4T(d0, d1, d2, d3, a) \
    asm volatile("ldmatrix.sync.aligned.m8n8.x4.trans.shared.b16 {%0,%1,%2,%3}, [%4];" \
                 : "=r"(d0), "=r"(d1), "=r"(d2), "=r"(d3) : "r"(a))
#define LDSM2T(d0, d1, a) \
    asm volatile("ldmatrix.sync.aligned.m8n8.x2.trans.shared.b16 {%0,%1}, [%2];" \
                 : "=r"(d0), "=r"(d1) : "r"(a))

#define CP16(dst, src) \
    asm volatile("cp.async.cg.shared.global [%0], [%1], 16;" \
                 :: "r"(dst), "l"(src) : "memory")
#define CP_COMMIT() asm volatile("cp.async.commit_group;" ::: "memory")
#define CP_WAIT1() asm volatile("cp.async.wait_group 1;" ::: "memory")
#define CP_WAIT0() asm volatile("cp.async.wait_group 0;" ::: "memory")

// ---------------------------------------------------------------------------
// fp32 -> fp16 conversion, one launch (blockIdx.y selects tensor).
// ---------------------------------------------------------------------------
__global__ void cvt_all(const float* __restrict__ x,  const float* __restrict__ wq,
                        const float* __restrict__ wk, const float* __restrict__ wv,
                        const float* __restrict__ wo) {
    const int sel = blockIdx.y;
    const float* src;
    __half* dst;
    int n4;
    if (sel == 0) { src = x;  dst = hx;                 n4 = M_TOTAL * DIM / 4; }
    else if (sel == 1) { src = wq; dst = hw;                n4 = DIM * DIM / 4; }
    else if (sel == 2) { src = wk; dst = hw + DIM * DIM;    n4 = DIM * DIM / 4; }
    else if (sel == 3) { src = wv; dst = hw + 2 * DIM * DIM; n4 = DIM * DIM / 4; }
    else { src = wo; dst = hw + 3 * DIM * DIM; n4 = DIM * DIM / 4; }
    int i = blockIdx.x * blockDim.x + threadIdx.x;
    int stride = gridDim.x * blockDim.x;
    for (; i < n4; i += stride) {
        float4 v = ((const float4*)src)[i];
        ((__half2*)dst)[2 * i] = __floats2half2_rn(v.x, v.y);
        ((__half2*)dst)[2 * i + 1] = __floats2half2_rn(v.z, v.w);
    }
}

// ---------------------------------------------------------------------------
// GEMM: Y[m][n] = sum_k X[m][k]*W[n][k] (x @ W.T), fp16 m16n8k16, f32 accum,
// ldmatrix loads, 2-stage cp.async, K-chunk 32 so 2 CTAs/SM co-reside.
// Block 128x128, 256 thr = 8 warps (4m x 2n).
// ---------------------------------------------------------------------------
#define PADH 40                               // halves per row (80 B)
#define GST_H (2 * 128 * PADH)                // A+B halves per stage (10240)
#define GEMM_SMEM (2 * GST_H * 2)             // 40960 B -> 2 CTAs/SM

__device__ __forceinline__ void gemm_body(const __half* __restrict__ X,
                                          const __half* __restrict__ W,
                                          __half* __restrict__ Yh,
                                          float* __restrict__ Yf) {
    extern __shared__ __half smg[];
    const int tid = threadIdx.x, lane = tid & 31, wid = tid >> 5;
    const int wm = wid & 3, wn = wid >> 2;
    const int mb = blockIdx.y * 128, nb = blockIdx.x * 128;
    const int lr = lane >> 2, lc = lane & 3;
    const uint32_t sb = smem_u32(smg);

    const int arow = (lane & 7) + ((lane >> 3) & 1) * 8;
    const int acol = (lane >> 4) * 8;
    const int brow = (lane & 7) + (lane >> 4) * 8;
    const int bcol = ((lane >> 3) & 1) * 8;

    uint32_t a_off[2], b_off[4];
#pragma unroll
    for (int mt = 0; mt < 2; mt++)
        a_off[mt] = (uint32_t)((wm * 32 + mt * 16 + arow) * PADH + acol) * 2;
#pragma unroll
    for (int p = 0; p < 4; p++)
        b_off[p] = (uint32_t)(128 * PADH + (wn * 64 + p * 16 + brow) * PADH + bcol) * 2;

    float acc[2][8][4];
#pragma unroll
    for (int i = 0; i < 2; i++)
#pragma unroll
        for (int j = 0; j < 8; j++)
#pragma unroll
            for (int c = 0; c < 4; c++) acc[i][j][c] = 0.0f;

    // 128 rows x 4 16B-chunks per matrix, x2 matrices = 1024 CP16; 4/thread.
    const int cr = tid >> 2, cc = tid & 3;    // rows 0..63, chunks 0..3
    auto issue = [&](int kt, int s) {
        const int k0 = kt * 32;
        uint32_t base = sb + (uint32_t)s * GST_H * 2;
#pragma unroll
        for (int t = 0; t < 4; t++) {
            int r = cr + (t >> 1) * 64;       // 0..127
            const __half* src = (t & 1) ? W + (size_t)(nb + r) * DIM + k0 + cc * 8
                                        : X + (size_t)(mb + r) * DIM + k0 + cc * 8;
            uint32_t dst = base + ((t & 1) ? (uint32_t)(128 * PADH * 2) : 0u) +
                           (uint32_t)(r * PADH + cc * 8) * 2;
            CP16(dst, src);
        }
        CP_COMMIT();
    };

    issue(0, 0);
    for (int kt = 0; kt < 16; kt++) {
        if (kt < 15) { issue(kt + 1, (kt + 1) & 1); CP_WAIT1(); }
        else CP_WAIT0();
        __syncthreads();

        const uint32_t sbs = sb + ((kt & 1) ? (uint32_t)GST_H * 2 : 0u);
#pragma unroll
        for (int ks = 0; ks < 2; ks++) {
            const uint32_t kkb = (uint32_t)(ks * 16) * 2;
            uint32_t a[2][4], b[8][2];
#pragma unroll
            for (int mt = 0; mt < 2; mt++)
                LDSM4(a[mt][0], a[mt][1], a[mt][2], a[mt][3],
                      sbs + a_off[mt] + kkb);
#pragma unroll
            for (int p = 0; p < 4; p++)
                LDSM4(b[2 * p][0], b[2 * p][1], b[2 * p + 1][0], b[2 * p + 1][1],
                      sbs + b_off[p] + kkb);
#pragma unroll
            for (int mt = 0; mt < 2; mt++)
#pragma unroll
                for (int nt = 0; nt < 8; nt++)
                    mma_f16(acc[mt][nt], a[mt], b[nt]);
        }
        __syncthreads();
    }

#pragma unroll
    for (int mt = 0; mt < 2; mt++) {
        int r0 = mb + wm * 32 + mt * 16 + lr;
#pragma unroll
        for (int nt = 0; nt < 8; nt++) {
            int c0 = nb + wn * 64 + nt * 8 + 2 * lc;
            if (Yf) {
                *(float2*)(Yf + (size_t)r0 * DIM + c0) =
                    make_float2(acc[mt][nt][0], acc[mt][nt][1]);
                *(float2*)(Yf + (size_t)(r0 + 8) * DIM + c0) =
                    make_float2(acc[mt][nt][2], acc[mt][nt][3]);
            } else {
                *(uint32_t*)(Yh + (size_t)r0 * DIM + c0) =
                    pack2(acc[mt][nt][0], acc[mt][nt][1]);
                *(uint32_t*)(Yh + (size_t)(r0 + 8) * DIM + c0) =
                    pack2(acc[mt][nt][2], acc[mt][nt][3]);
            }
        }
    }
}

__global__ __launch_bounds__(256, 2) void qkv_gemm() {
    const int z = blockIdx.z;
    __half* Y = (z == 0) ? g_q : (z == 1) ? g_k : g_v;
    gemm_body(hx, hw + (size_t)z * DIM * DIM, Y, nullptr);
}

__global__ __launch_bounds__(256, 2) void out_gemm(float* __restrict__ out) {
    gemm_body(g_o, hw + 3 * (size_t)DIM * DIM, nullptr, out);
}

// ---------------------------------------------------------------------------
// Flash attention, fp16 m16n8k16, 256-thr CTA (q-tile 64) so 2 CTAs/SM
// co-reside. Q pre-scaled by SCALE, l via ones-column mma, ldmatrix loads,
// 2-stage cp.async over 64-key tiles, key-split warp pairs.
// 8 warps: wq_=wid>>1 (0..3) owns q rows [wq_*16,+16); wk_=wid&1 owns keys
// [wk_*32,+32) of each 64-key tile.
// ---------------------------------------------------------------------------
#define PADA 72
#define KS_H (64 * PADA)                      // 4608 halves per K tile
#define ASTAGE_H (2 * KS_H)                   // K + V per stage
#define ATTN_SMEM (2 * ASTAGE_H * 2)          // 36864 B -> 2 CTAs/SM

__global__ __launch_bounds__(256, 2) void attn_f16() {
    extern __shared__ __half smh[];
    const int tid = threadIdx.x, lane = tid & 31, wid = tid >> 5;
    const int lr = lane >> 2, lc = lane & 3;
    const int wq_ = wid >> 1, wk_ = wid & 1;
    const int bh = blockIdx.y, b_ = bh >> 3, h_ = bh & 7;
    const int q0 = blockIdx.x * 64;
    const uint32_t sb = smem_u32(smh);

    const __half* Qg = g_q + (size_t)b_ * L * DIM + h_ * 64;
    const __half* Kg = g_k + (size_t)b_ * L * DIM + h_ * 64;
    const __half* Vg = g_v + (size_t)b_ * L * DIM + h_ * 64;

    const int arow = (lane & 7) + ((lane >> 3) & 1) * 8;
    const int acol = (lane >> 4) * 8;
    const int brow = (lane & 7) + (lane >> 4) * 8;
    const int bcol = ((lane >> 3) & 1) * 8;

    uint32_t k_off[2];
#pragma unroll
    for (int p = 0; p < 2; p++)
        k_off[p] = (uint32_t)((wk_ * 32 + p * 16 + brow) * PADA + bcol) * 2;
    const uint32_t v_roff = (uint32_t)(arow * PADA) * 2;
    const uint32_t v_l_off = (uint32_t)((lane & 15) * PADA + 64) * 2;

    // cp.async one 64-key K/V stage: 64 rows x 8 chunks x2 = 1024; 4/thread.
    const int ar = tid >> 3, ac = tid & 7;    // rows 0..31, chunks 0..7
    auto issue = [&](int t, int s) {
        const int k0g = t * 64;
        uint32_t base = sb + (uint32_t)s * ASTAGE_H * 2;
#pragma unroll
        for (int u = 0; u < 2; u++) {
            int r = ar + u * 32;              // 0..63
            CP16(base + (uint32_t)(r * PADA + ac * 8) * 2,
                 Kg + (size_t)(k0g + r) * DIM + ac * 8);
            CP16(base + (uint32_t)(KS_H + r * PADA + ac * 8) * 2,
                 Vg + (size_t)(k0g + r) * DIM + ac * 8);
        }
        CP_COMMIT();
    };

    issue(0, 0);                              // stage0 <- keys 0..63

    // Stage Q (scaled by SCALE, exact in fp16) into stage1 K region.
    __half* Qs = smh + ASTAGE_H;              // 64 x 72 <= 4608 halves
    {
        const __half2 sc = __half2half2(__float2half(SCALE));
#pragma unroll
        for (int t = 0; t < 2; t++) {
            int idx = tid + t * 256;          // 0..511
            int r = idx >> 3, c = idx & 7;
            uint4 q4 = *(const uint4*)(Qg + (size_t)(q0 + r) * DIM + c * 8);
            __half2* qh = (__half2*)&q4;
#pragma unroll
            for (int j = 0; j < 4; j++) qh[j] = __hmul2(qh[j], sc);
            *(uint4*)&Qs[r * PADA + c * 8] = q4;
        }
    }
    // Ones-column init in V padding (both stages): col 64 = 1, 65..71 = 0.
    if (tid < 128) {
        int s_ = tid >> 6, r = tid & 63;
        __half* p = smh + s_ * ASTAGE_H + KS_H + r * PADA + 64;
        *(uint4*)p = make_uint4(0x00003C00u, 0u, 0u, 0u);
    }
    __syncthreads();
    uint32_t aq[4][4];
    {
        uint32_t qbase = sb + (uint32_t)ASTAGE_H * 2 +
                         (uint32_t)((wq_ * 16 + arow) * PADA + acol) * 2;
#pragma unroll
        for (int ks = 0; ks < 4; ks++)
            LDSM4(aq[ks][0], aq[ks][1], aq[ks][2], aq[ks][3],
                  qbase + (uint32_t)(ks * 16) * 2);
    }
    __syncthreads();                          // stage1 free for tile1

    float o[8][4], o_l[4];
#pragma unroll
    for (int nt = 0; nt < 8; nt++)
#pragma unroll
        for (int c = 0; c < 4; c++) o[nt][c] = 0.0f;
#pragma unroll
    for (int c = 0; c < 4; c++) o_l[c] = 0.0f;

    const int row0 = q0 + wq_ * 16 + lr;
    const int row1 = row0 + 8;

    for (int t = 0; t < 32; t++) {
        if (t < 31) { issue(t + 1, (t + 1) & 1); CP_WAIT1(); }
        else CP_WAIT0();
        __syncthreads();

        const uint32_t sbs = sb + ((t & 1) ? (uint32_t)ASTAGE_H * 2 : 0u);
        const int k0g = t * 64;

        // S = Q @ K^T : 16 q x 32 keys per warp.
        float s[4][4];
#pragma unroll
        for (int nt = 0; nt < 4; nt++)
#pragma unroll
            for (int c = 0; c < 4; c++) s[nt][c] = 0.0f;
#pragma unroll
        for (int ks = 0; ks < 4; ks++) {
            const uint32_t kkb = (uint32_t)(ks * 16) * 2;
            uint32_t bk[4][2];
#pragma unroll
            for (int p = 0; p < 2; p++)
                LDSM4(bk[2 * p][0], bk[2 * p][1],
                      bk[2 * p + 1][0], bk[2 * p + 1][1],
                      sbs + k_off[p] + kkb);
#pragma unroll
            for (int nt = 0; nt < 4; nt++) mma_f16(s[nt], aq[ks], bk[nt]);
        }

        // p = exp(s) (Q pre-scaled); diagonal -> 0.
#pragma unroll
        for (int nt = 0; nt < 4; nt++) {
            int key = k0g + wk_ * 32 + nt * 8 + 2 * lc;
            float p0 = __expf(s[nt][0]);
            float p1 = __expf(s[nt][1]);
            float p2 = __expf(s[nt][2]);
            float p3 = __expf(s[nt][3]);
            if (key == row0) p0 = 0.0f;
            if (key + 1 == row0) p1 = 0.0f;
            if (key == row1) p2 = 0.0f;
            if (key + 1 == row1) p3 = 0.0f;
            s[nt][0] = p0; s[nt][1] = p1; s[nt][2] = p2; s[nt][3] = p3;
        }

        // O += P @ V; l += P @ ones (V pad column).
#pragma unroll
        for (int ksl = 0; ksl < 2; ksl++) {
            uint32_t ap[4];
            ap[0] = pack2(s[2 * ksl][0], s[2 * ksl][1]);
            ap[1] = pack2(s[2 * ksl][2], s[2 * ksl][3]);
            ap[2] = pack2(s[2 * ksl + 1][0], s[2 * ksl + 1][1]);
            ap[3] = pack2(s[2 * ksl + 1][2], s[2 * ksl + 1][3]);

            const int kkv = wk_ * 32 + ksl * 16;
            const uint32_t vb = sbs + (uint32_t)KS_H * 2 +
                                (uint32_t)(kkv * PADA) * 2;
            uint32_t bv[8][2];
#pragma unroll
            for (int p = 0; p < 4; p++)
                LDSM4T(bv[2 * p][0], bv[2 * p][1],
                       bv[2 * p + 1][0], bv[2 * p + 1][1],
                       vb + v_roff + (uint32_t)acol * 2 +
                       (uint32_t)(p * 16) * 2);
#pragma unroll
            for (int nt = 0; nt < 8; nt++) mma_f16(o[nt], ap, bv[nt]);

            uint32_t bl[2];
            LDSM2T(bl[0], bl[1], vb + v_l_off);
            mma_f16(o_l, ap, bl);
        }
        __syncthreads();
    }

    // Merge key-half pairs via smem: o (32) + o_l (4) per thread.
    float* OS = (float*)smh;                  // [4][32][36] = 18432 B
    if (wk_ == 1) {
        float* dst = OS + ((size_t)wq_ * 32 + lane) * 36;
#pragma unroll
        for (int nt = 0; nt < 8; nt++)
#pragma unroll
            for (int c = 0; c < 4; c++) dst[nt * 4 + c] = o[nt][c];
#pragma unroll
        for (int c = 0; c < 4; c++) dst[32 + c] = o_l[c];
    }
    __syncthreads();
    if (wk_ == 0) {
        const float* srcp = OS + ((size_t)wq_ * 32 + lane) * 36;
#pragma unroll
        for (int nt = 0; nt < 8; nt++)
#pragma unroll
            for (int c = 0; c < 4; c++) o[nt][c] += srcp[nt * 4 + c];
#pragma unroll
        for (int c = 0; c < 4; c++) o_l[c] += srcp[32 + c];

        // l lives in col 64 -> lc==0 lanes; broadcast within quad.
        float l0 = __shfl_sync(0xffffffffu, o_l[0], lane & 28);
        float l1 = __shfl_sync(0xffffffffu, o_l[2], lane & 28);
        const float inv0 = 1.0f / l0, inv1 = 1.0f / l1;
        __half* Og = g_o + ((size_t)b_ * L) * DIM + h_ * 64;
#pragma unroll
        for (int nt = 0; nt < 8; nt++) {
            int c0 = nt * 8 + 2 * lc;
            *(uint32_t*)(Og + (size_t)row0 * DIM + c0) =
                pack2(o[nt][0] * inv0, o[nt][1] * inv0);
            *(uint32_t*)(Og + (size_t)row1 * DIM + c0) =
                pack2(o[nt][2] * inv1, o[nt][3] * inv1);
        }
    }
}

// ---------------------------------------------------------------------------
extern "C" void kernel_launch(void* const* d_in, const int* in_sizes, int n_in,
                              void* d_out, int out_size) {
    const float* x  = (const float*)d_in[0];
    const float* wq = (const float*)d_in[1];
    const float* wk = (const float*)d_in[2];
    const float* wv = (const float*)d_in[3];
    const float* wo = (const float*)d_in[4];
    float* out = (float*)d_out;

    cudaFuncSetAttribute(qkv_gemm, cudaFuncAttributeMaxDynamicSharedMemorySize,
                         GEMM_SMEM);
    cudaFuncSetAttribute(out_gemm, cudaFuncAttributeMaxDynamicSharedMemorySize,
                         GEMM_SMEM);
    cudaFuncSetAttribute(attn_f16, cudaFuncAttributeMaxDynamicSharedMemorySize,
                         ATTN_SMEM);
    cudaFuncSetAttribute(qkv_gemm, cudaFuncAttributePreferredSharedMemoryCarveout, 100);
    cudaFuncSetAttribute(out_gemm, cudaFuncAttributePreferredSharedMemoryCarveout, 100);
    cudaFuncSetAttribute(attn_f16, cudaFuncAttributePreferredSharedMemoryCarveout, 100);

    cvt_all<<<dim3(128, 5), 256>>>(x, wq, wk, wv, wo);
    qkv_gemm<<<dim3(4, 64, 3), 256, GEMM_SMEM>>>();
    attn_f16<<<dim3(L / 64, B * H), 256, ATTN_SMEM>>>();
    out_gemm<<<dim3(4, 64), 256, GEMM_SMEM>>>(out);
}